// round 2
// baseline (speedup 1.0000x reference)
#include <cuda_runtime.h>
#include <cuda_bf16.h>
#include <cstddef>

// Scratch: transposed x, point-major: g_xt[gp*8 + b]. 512*512*8 floats = 8 MB.
#define MAX_N (512 * 512)
#define NB 8
__device__ float g_xt[(size_t)MAX_N * NB];

// ---------------------------------------------------------------------------
// Kernel 1: transpose x[b][gp] -> g_xt[gp][b]  (B == 8 fast path)
// Loads coalesced across gp for each b; stores 2x STG.128, fully coalesced.
// ---------------------------------------------------------------------------
__global__ void transpose8_kernel(const float* __restrict__ x, int N) {
    int gp = blockIdx.x * blockDim.x + threadIdx.x;
    if (gp >= N) return;
    float v[NB];
#pragma unroll
    for (int b = 0; b < NB; b++) v[b] = __ldg(&x[(size_t)b * N + gp]);
    float4* dst = reinterpret_cast<float4*>(&g_xt[(size_t)gp * NB]);
    dst[0] = make_float4(v[0], v[1], v[2], v[3]);
    dst[1] = make_float4(v[4], v[5], v[6], v[7]);
}

// ---------------------------------------------------------------------------
// Kernel 2: simplex interpolation, B==8 fast path.
// Per target: 3 grid-point gathers of 32B each (all 8 batches at once).
// ---------------------------------------------------------------------------
__global__ void __launch_bounds__(256) interp8_kernel(
    const float* __restrict__ src_x,
    const float* __restrict__ src_y,
    const float* __restrict__ tgt_x,
    const float* __restrict__ tgt_y,
    const int* __restrict__ p_nx,
    const int* __restrict__ p_ny,
    float* __restrict__ out,
    int T)
{
    int t = blockIdx.x * blockDim.x + threadIdx.x;
    if (t >= T) return;

    // Uniform scalars (L1-resident broadcast loads after first warp).
    const int nx = p_nx[0];
    const int ny = p_ny[0];
    const float x0 = src_x[0];
    const float x1 = src_x[nx - 1];
    const float y0 = src_y[0];
    const float y1 = src_y[(size_t)(ny - 1) * nx];
    const float inv_dx = (float)(nx - 1) / (x1 - x0);
    const float inv_dy = (float)(ny - 1) / (y1 - y0);

    const float fx = (tgt_x[t] - x0) * inv_dx;
    const float fy = (tgt_y[t] - y0) * inv_dy;

    float ixf = floorf(fx);
    ixf = fminf(fmaxf(ixf, 0.0f), (float)(nx - 2));
    float iyf = floorf(fy);
    iyf = fminf(fmaxf(iyf, 0.0f), (float)(ny - 2));

    const float u = fx - ixf;
    const float v = fy - iyf;
    const int ii = (int)ixf;
    const int jj = (int)iyf;
    const int base = jj * nx + ii;

    const bool lower = (u + v <= 1.0f);
    // Shared vertices: B = base+1, C = base+nx. Third vertex A depends on half.
    const int iA = lower ? base : (base + nx + 1);
    const int iB = base + 1;
    const int iC = base + nx;
    const float wA = lower ? (1.0f - u - v) : (u + v - 1.0f);
    const float wB = lower ? u : (1.0f - v);
    const float wC = lower ? v : (1.0f - u);

    const float4* __restrict__ xt = reinterpret_cast<const float4*>(g_xt);
    const float4 a0 = __ldg(&xt[(size_t)iA * 2]);
    const float4 a1 = __ldg(&xt[(size_t)iA * 2 + 1]);
    const float4 b0 = __ldg(&xt[(size_t)iB * 2]);
    const float4 b1 = __ldg(&xt[(size_t)iB * 2 + 1]);
    const float4 c0 = __ldg(&xt[(size_t)iC * 2]);
    const float4 c1 = __ldg(&xt[(size_t)iC * 2 + 1]);

    float o[NB];
    o[0] = wA * a0.x + wB * b0.x + wC * c0.x;
    o[1] = wA * a0.y + wB * b0.y + wC * c0.y;
    o[2] = wA * a0.z + wB * b0.z + wC * c0.z;
    o[3] = wA * a0.w + wB * b0.w + wC * c0.w;
    o[4] = wA * a1.x + wB * b1.x + wC * c1.x;
    o[5] = wA * a1.y + wB * b1.y + wC * c1.y;
    o[6] = wA * a1.z + wB * b1.z + wC * c1.z;
    o[7] = wA * a1.w + wB * b1.w + wC * c1.w;

#pragma unroll
    for (int b = 0; b < NB; b++)
        out[(size_t)b * T + t] = o[b];  // coalesced per-b
}

// ---------------------------------------------------------------------------
// Generic fallback (any B): gathers straight from x[b][i]. Correct but slower.
// ---------------------------------------------------------------------------
__global__ void interp_generic_kernel(
    const float* __restrict__ x,
    const float* __restrict__ src_x,
    const float* __restrict__ src_y,
    const float* __restrict__ tgt_x,
    const float* __restrict__ tgt_y,
    const int* __restrict__ p_nx,
    const int* __restrict__ p_ny,
    float* __restrict__ out,
    int T, int B, int N)
{
    int t = blockIdx.x * blockDim.x + threadIdx.x;
    if (t >= T) return;

    const int nx = p_nx[0];
    const int ny = p_ny[0];
    const float x0 = src_x[0];
    const float x1 = src_x[nx - 1];
    const float y0 = src_y[0];
    const float y1 = src_y[(size_t)(ny - 1) * nx];
    const float inv_dx = (float)(nx - 1) / (x1 - x0);
    const float inv_dy = (float)(ny - 1) / (y1 - y0);

    const float fx = (tgt_x[t] - x0) * inv_dx;
    const float fy = (tgt_y[t] - y0) * inv_dy;

    float ixf = fminf(fmaxf(floorf(fx), 0.0f), (float)(nx - 2));
    float iyf = fminf(fmaxf(floorf(fy), 0.0f), (float)(ny - 2));
    const float u = fx - ixf;
    const float v = fy - iyf;
    const int base = (int)iyf * nx + (int)ixf;

    const bool lower = (u + v <= 1.0f);
    const int iA = lower ? base : (base + nx + 1);
    const int iB = base + 1;
    const int iC = base + nx;
    const float wA = lower ? (1.0f - u - v) : (u + v - 1.0f);
    const float wB = lower ? u : (1.0f - v);
    const float wC = lower ? v : (1.0f - u);

    for (int b = 0; b < B; b++) {
        const float* xb = x + (size_t)b * N;
        out[(size_t)b * T + t] = wA * xb[iA] + wB * xb[iB] + wC * xb[iC];
    }
}

extern "C" void kernel_launch(void* const* d_in, const int* in_sizes, int n_in,
                              void* d_out, int out_size)
{
    const float* x     = (const float*)d_in[0];
    const float* src_x = (const float*)d_in[1];
    const float* src_y = (const float*)d_in[2];
    const float* tgt_x = (const float*)d_in[3];
    const float* tgt_y = (const float*)d_in[4];
    const int*   p_nx  = (const int*)d_in[5];
    const int*   p_ny  = (const int*)d_in[6];
    float* out = (float*)d_out;

    const int N = in_sizes[1];          // nx*ny grid points
    const int T = in_sizes[3];          // target count
    const int B = in_sizes[0] / N;      // batches

    const int threads = 256;
    if (B == NB && N <= MAX_N) {
        transpose8_kernel<<<(N + threads - 1) / threads, threads>>>(x, N);
        interp8_kernel<<<(T + threads - 1) / threads, threads>>>(
            src_x, src_y, tgt_x, tgt_y, p_nx, p_ny, out, T);
    } else {
        interp_generic_kernel<<<(T + threads - 1) / threads, threads>>>(
            x, src_x, src_y, tgt_x, tgt_y, p_nx, p_ny, out, T, B, N);
    }
}

// round 3
// speedup vs baseline: 1.1651x; 1.1651x over previous
#include <cuda_runtime.h>
#include <cuda_bf16.h>
#include <cstddef>

// Scratch: transposed x, point-major: g_xt[gp*8 + b]. 512*512*8 floats = 8 MB.
#define MAX_N (512 * 512)
#define NB 8
__device__ float g_xt[(size_t)MAX_N * NB];

// ---------------------------------------------------------------------------
// Kernel 1: transpose x[b][gp] -> g_xt[gp][b]  (B == 8 fast path)
// ---------------------------------------------------------------------------
__global__ void transpose8_kernel(const float* __restrict__ x, int N) {
    int gp = blockIdx.x * blockDim.x + threadIdx.x;
    if (gp >= N) return;
    float v[NB];
#pragma unroll
    for (int b = 0; b < NB; b++) v[b] = __ldg(&x[(size_t)b * N + gp]);
    float4* dst = reinterpret_cast<float4*>(&g_xt[(size_t)gp * NB]);
    dst[0] = make_float4(v[0], v[1], v[2], v[3]);
    dst[1] = make_float4(v[4], v[5], v[6], v[7]);
}

// ---------------------------------------------------------------------------
// Kernel 2: cooperative-lane simplex interpolation (B == 8).
//
// Warp layout: 32 lanes = 8 target-quads x 4 batch-pairs.
//   lane = q*4 + p : handles targets tq..tq+3 (tq = warpT0 + 4q),
//                    batches 2p and 2p+1 (a float2 slice of the 32B point).
// Per warp (32 targets):
//   - gathers: 12 x LDG.64, each touching ~8 distinct lines -> ~1 wf/target-vertex
//   - tgt coords: 2 x LDG.128, 128B-coherent across quads -> ~2 wf total
//   - stores: 2 x STG.128 per lane; 8 quads form one full 128B line per batch
// ---------------------------------------------------------------------------
__global__ void __launch_bounds__(256) interp8_coop_kernel(
    const float* __restrict__ src_x,
    const float* __restrict__ src_y,
    const float* __restrict__ tgt_x,
    const float* __restrict__ tgt_y,
    const int* __restrict__ p_nx,
    const int* __restrict__ p_ny,
    float* __restrict__ out,
    int T)
{
    const int lane = threadIdx.x & 31;
    const int warp = (blockIdx.x * blockDim.x + threadIdx.x) >> 5;
    const int q    = lane >> 2;      // target quad within warp (0..7)
    const int pair = lane & 3;       // batch pair (handles b=2*pair, 2*pair+1)
    const int tq   = warp * 32 + q * 4;  // first of this lane's 4 targets
    if (tq >= T) return;

    // Uniform scalars (uniform-path loads).
    const int nx = p_nx[0];
    const int ny = p_ny[0];
    const float x0 = src_x[0];
    const float x1 = src_x[nx - 1];
    const float y0 = src_y[0];
    const float y1 = src_y[(size_t)(ny - 1) * nx];
    const float inv_dx = (float)(nx - 1) / (x1 - x0);
    const float inv_dy = (float)(ny - 1) / (y1 - y0);
    const float nxm2 = (float)(nx - 2);
    const float nym2 = (float)(ny - 2);

    const bool full = (tq + 3 < T);

    float tx[4], ty[4];
    if (full) {
        const float4 tx4 = *reinterpret_cast<const float4*>(tgt_x + tq);
        const float4 ty4 = *reinterpret_cast<const float4*>(tgt_y + tq);
        tx[0] = tx4.x; tx[1] = tx4.y; tx[2] = tx4.z; tx[3] = tx4.w;
        ty[0] = ty4.x; ty[1] = ty4.y; ty[2] = ty4.z; ty[3] = ty4.w;
    } else {
#pragma unroll
        for (int j = 0; j < 4; j++) {
            int t = min(tq + j, T - 1);
            tx[j] = tgt_x[t];
            ty[j] = tgt_y[t];
        }
    }

    int   iA[4], iB[4], iC[4];
    float wA[4], wB[4], wC[4];
#pragma unroll
    for (int j = 0; j < 4; j++) {
        const float fx = (tx[j] - x0) * inv_dx;
        const float fy = (ty[j] - y0) * inv_dy;
        const float ixf = fminf(fmaxf(floorf(fx), 0.0f), nxm2);
        const float iyf = fminf(fmaxf(floorf(fy), 0.0f), nym2);
        const float u = fx - ixf;
        const float v = fy - iyf;
        const int base = (int)iyf * nx + (int)ixf;
        const bool lower = (u + v <= 1.0f);
        iA[j] = lower ? base : (base + nx + 1);
        iB[j] = base + 1;
        iC[j] = base + nx;
        wA[j] = lower ? (1.0f - u - v) : (u + v - 1.0f);
        wB[j] = lower ? u : (1.0f - v);
        wC[j] = lower ? v : (1.0f - u);
    }

    // Gather: float2 slice (batches 2p,2p+1) of each 32B point record.
    const float2* __restrict__ xt2 = reinterpret_cast<const float2*>(g_xt);
    float2 vA[4], vB[4], vC[4];
#pragma unroll
    for (int j = 0; j < 4; j++) vA[j] = __ldg(&xt2[(size_t)iA[j] * 4 + pair]);
#pragma unroll
    for (int j = 0; j < 4; j++) vB[j] = __ldg(&xt2[(size_t)iB[j] * 4 + pair]);
#pragma unroll
    for (int j = 0; j < 4; j++) vC[j] = __ldg(&xt2[(size_t)iC[j] * 4 + pair]);

    float o0[4], o1[4];  // batch 2*pair, 2*pair+1
#pragma unroll
    for (int j = 0; j < 4; j++) {
        o0[j] = wA[j] * vA[j].x + wB[j] * vB[j].x + wC[j] * vC[j].x;
        o1[j] = wA[j] * vA[j].y + wB[j] * vB[j].y + wC[j] * vC[j].y;
    }

    const int b0 = 2 * pair;
    if (full) {
        *reinterpret_cast<float4*>(out + (size_t)b0 * T + tq) =
            make_float4(o0[0], o0[1], o0[2], o0[3]);
        *reinterpret_cast<float4*>(out + (size_t)(b0 + 1) * T + tq) =
            make_float4(o1[0], o1[1], o1[2], o1[3]);
    } else {
#pragma unroll
        for (int j = 0; j < 4; j++) {
            if (tq + j < T) {
                out[(size_t)b0 * T + tq + j] = o0[j];
                out[(size_t)(b0 + 1) * T + tq + j] = o1[j];
            }
        }
    }
}

// ---------------------------------------------------------------------------
// Generic fallback (any B).
// ---------------------------------------------------------------------------
__global__ void interp_generic_kernel(
    const float* __restrict__ x,
    const float* __restrict__ src_x,
    const float* __restrict__ src_y,
    const float* __restrict__ tgt_x,
    const float* __restrict__ tgt_y,
    const int* __restrict__ p_nx,
    const int* __restrict__ p_ny,
    float* __restrict__ out,
    int T, int B, int N)
{
    int t = blockIdx.x * blockDim.x + threadIdx.x;
    if (t >= T) return;

    const int nx = p_nx[0];
    const int ny = p_ny[0];
    const float x0 = src_x[0];
    const float x1 = src_x[nx - 1];
    const float y0 = src_y[0];
    const float y1 = src_y[(size_t)(ny - 1) * nx];
    const float inv_dx = (float)(nx - 1) / (x1 - x0);
    const float inv_dy = (float)(ny - 1) / (y1 - y0);

    const float fx = (tgt_x[t] - x0) * inv_dx;
    const float fy = (tgt_y[t] - y0) * inv_dy;

    float ixf = fminf(fmaxf(floorf(fx), 0.0f), (float)(nx - 2));
    float iyf = fminf(fmaxf(floorf(fy), 0.0f), (float)(ny - 2));
    const float u = fx - ixf;
    const float v = fy - iyf;
    const int base = (int)iyf * nx + (int)ixf;

    const bool lower = (u + v <= 1.0f);
    const int iA = lower ? base : (base + nx + 1);
    const int iB = base + 1;
    const int iC = base + nx;
    const float wA = lower ? (1.0f - u - v) : (u + v - 1.0f);
    const float wB = lower ? u : (1.0f - v);
    const float wC = lower ? v : (1.0f - u);

    for (int b = 0; b < B; b++) {
        const float* xb = x + (size_t)b * N;
        out[(size_t)b * T + t] = wA * xb[iA] + wB * xb[iB] + wC * xb[iC];
    }
}

extern "C" void kernel_launch(void* const* d_in, const int* in_sizes, int n_in,
                              void* d_out, int out_size)
{
    const float* x     = (const float*)d_in[0];
    const float* src_x = (const float*)d_in[1];
    const float* src_y = (const float*)d_in[2];
    const float* tgt_x = (const float*)d_in[3];
    const float* tgt_y = (const float*)d_in[4];
    const int*   p_nx  = (const int*)d_in[5];
    const int*   p_ny  = (const int*)d_in[6];
    float* out = (float*)d_out;

    const int N = in_sizes[1];          // nx*ny grid points
    const int T = in_sizes[3];          // target count
    const int B = in_sizes[0] / N;      // batches

    const int threads = 256;
    if (B == NB && N <= MAX_N) {
        transpose8_kernel<<<(N + threads - 1) / threads, threads>>>(x, N);
        // One warp covers 32 targets; one 256-thread block covers 256 targets.
        const int blocks = (T + 255) / 256;
        interp8_coop_kernel<<<blocks, threads>>>(
            src_x, src_y, tgt_x, tgt_y, p_nx, p_ny, out, T);
    } else {
        interp_generic_kernel<<<(T + threads - 1) / threads, threads>>>(
            x, src_x, src_y, tgt_x, tgt_y, p_nx, p_ny, out, T, B, N);
    }
}